// round 15
// baseline (speedup 1.0000x reference)
#include <cuda_runtime.h>
#include <cuda_fp16.h>
#include <cstdint>

#define BATCH   64
#define SEQ     1024
#define IDIM    128
#define HDIM    512
#define G4      2048
#define KTOT    640
#define NGRP    4
#define GB      16
#define NCTA    32
#define HC      16
#define NL      64
#define THREADS 128
#define NCH_H   32
#define NCH_X   8
#define NCH     40

#define ZSTR     648
#define OFF_Z    0
#define OFF_A0   (NL * ZSTR * 2)            // 82944 : staging buf 0 (16KB)
#define OFF_A1   (OFF_A0 + NCH_H * 512)     // 99328 : staging buf 1 (16KB)
#define OFF_MBAR (OFF_A1 + NCH_H * 512)     // 115712
#define SMEM_SZ  (OFF_MBAR + 16)            // 115728 B

// ---- global scratch (static) -------------------------------------------------
__device__ uint32_t g_xfrag[(size_t)NGRP * SEQ * NCH_X * 128];  // x in frag layout
__device__ uint32_t g_hfrag[2 * NGRP * NCTA * 128];             // ping-pong h chunks
__device__ float    g_hfin[BATCH][HDIM];                        // exact final h
__device__ int      g_step[NGRP][32];                           // 128B-padded counter
__device__ int      g_cnt, g_gen;

// ---- prologue-only global barrier (replay-safe) ------------------------------
__device__ __forceinline__ void bar_all(int n)
{
    int my;
    asm volatile("ld.acquire.gpu.global.b32 %0, [%1];" : "=r"(my) : "l"(&g_gen));
    __threadfence();
    if (atomicAdd(&g_cnt, 1) == n - 1) {
        atomicExch(&g_cnt, 0);
        __threadfence();
        atomicAdd(&g_gen, 1);
    } else {
        int v;
        do { asm volatile("ld.acquire.gpu.global.b32 %0, [%1];" : "=r"(v) : "l"(&g_gen)); }
        while (v == my);
    }
}

// single-line poll + single-counter release (validated best, R6/R9/R14)
__device__ __forceinline__ void poll_cnt(int g, int need)
{
    const int* p = &g_step[g][0];
    int v;
    do { asm volatile("ld.acquire.gpu.global.b32 %0, [%1];" : "=r"(v) : "l"(p)); }
    while (v < need);
}
__device__ __forceinline__ void release_inc(int g)
{
    asm volatile("red.add.release.gpu.global.s32 [%0], 1;" :: "l"(&g_step[g][0]) : "memory");
}

__device__ __forceinline__ void cpasync16(uint32_t dst, const void* src)
{
    asm volatile("cp.async.cg.shared.global [%0], [%1], 16;" :: "r"(dst), "l"(src));
}
// .noinc is load-bearing (R8 deadlock without it)
__device__ __forceinline__ void cp_mbar_arrive(uint32_t mbar)
{
    asm volatile("cp.async.mbarrier.arrive.noinc.shared::cta.b64 [%0];"
                 :: "r"(mbar) : "memory");
}
__device__ __forceinline__ void mbar_init(uint32_t mbar, int cnt)
{
    asm volatile("mbarrier.init.shared.b64 [%0], %1;" :: "r"(mbar), "r"(cnt) : "memory");
}
__device__ __forceinline__ void mbar_wait(uint32_t mbar, uint32_t parity)
{
    asm volatile(
        "{\n\t"
        ".reg .pred P;\n\t"
        "WAIT_%=:\n\t"
        "mbarrier.try_wait.parity.acquire.cta.shared::cta.b64 P, [%0], %1, 0x989680;\n\t"
        "@P bra.uni DONE_%=;\n\t"
        "bra.uni WAIT_%=;\n\t"
        "DONE_%=:\n\t"
        "}"
        :: "r"(mbar), "r"(parity) : "memory");
}

__device__ __forceinline__ void lds128(unsigned r[4], uint32_t a)
{
    asm volatile("ld.shared.v4.b32 {%0,%1,%2,%3}, [%4];"
                 : "=r"(r[0]), "=r"(r[1]), "=r"(r[2]), "=r"(r[3]) : "r"(a));
}
__device__ __forceinline__ void ldsm4(unsigned r[4], uint32_t a)
{
    asm volatile("ldmatrix.sync.aligned.m8n8.x4.shared.b16 {%0,%1,%2,%3}, [%4];"
                 : "=r"(r[0]), "=r"(r[1]), "=r"(r[2]), "=r"(r[3]) : "r"(a));
}
__device__ __forceinline__ void mma_f16(float* d, const unsigned* a, const unsigned* b)
{
    asm volatile(
        "mma.sync.aligned.m16n8k16.row.col.f32.f16.f16.f32 "
        "{%0,%1,%2,%3}, {%4,%5,%6,%7}, {%8,%9}, {%0,%1,%2,%3};\n"
        : "+f"(d[0]), "+f"(d[1]), "+f"(d[2]), "+f"(d[3])
        : "r"(a[0]), "r"(a[1]), "r"(a[2]), "r"(a[3]), "r"(b[0]), "r"(b[1]));
}

// fast activations (validated R14): single tanh.approx MUFU each
__device__ __forceinline__ float ftanh_f(float x)
{
    float y;
    asm("tanh.approx.f32 %0, %1;" : "=f"(y) : "f"(x));
    return y;
}
__device__ __forceinline__ float fsig_f(float x)
{
    return fmaf(0.5f, ftanh_f(0.5f * x), 0.5f);
}

// ---- x -> fp16 fragment-ready layout (validated) -----------------------------
extern "C" __global__ void xsplit_kernel(const float* __restrict__ x)
{
    int gid = blockIdx.x * 256 + threadIdx.x;
    int i0 = (gid & 31) * 4;
    int s  = (gid >> 5) & (SEQ - 1);
    int b  = gid >> 15;
    float4 v = *(const float4*)(x + ((size_t)b * SEQ + s) * IDIM + i0);
    int bl = b & 15, grp = b >> 4;
    int kx = i0 >> 4, kl = i0 & 15;
    int lane = ((bl & 7) << 2) | ((kl & 7) >> 1);
    int j    = ((kl >> 3) << 1) | (bl >> 3);
    uint32_t u0 = (uint32_t)__half_as_ushort(__float2half(v.x)) |
                  ((uint32_t)__half_as_ushort(__float2half(v.y)) << 16);
    uint32_t u1 = (uint32_t)__half_as_ushort(__float2half(v.z)) |
                  ((uint32_t)__half_as_ushort(__float2half(v.w)) << 16);
    size_t base = (((size_t)grp * SEQ + s) * NCH_X + kx) * 128;
    g_xfrag[base + lane * 4 + j]       = u0;
    g_xfrag[base + (lane + 1) * 4 + j] = u1;
}

// ---- persistent LSTM: R14 + gate-complete column remap (shfl-free gates) -----
extern "C" __global__ void __launch_bounds__(THREADS, 1)
lstm_kernel(const float* __restrict__ W, const float* __restrict__ U,
            const float* __restrict__ bias,
            const float* __restrict__ fc_w, const float* __restrict__ fc_b,
            float* __restrict__ out)
{
    extern __shared__ char smem[];
    __half* zh = (__half*)(smem + OFF_Z);

    const int tid  = threadIdx.x;
    const int lane = tid & 31;
    const int warp = tid >> 5;
    const int grp  = blockIdx.x >> 5;
    const int gc   = blockIdx.x & 31;
    const int b0   = grp * GB;
    const int h0   = gc * HC;
    const uint32_t smb  = (uint32_t)__cvta_generic_to_shared(smem);
    const uint32_t mbar = smb + OFF_MBAR;

    // weights: gate-complete per-thread mapping.
    // local col nl = warp_w*16 + n ; j=(n>>1)&3 ; gate=(n&1)|((n>>3)<<1) ;
    // hid = warp_w*4 + j  -> thread (warp,j) owns all 4 gates of its hid.
    for (int idx = tid; idx < KTOT * NL; idx += THREADS) {
        int k = idx >> 6, nl = idx & 63;
        int warp_w = nl >> 4, n = nl & 15;
        int jj   = (n >> 1) & 3;
        int gate = (n & 1) | ((n >> 3) << 1);
        int col  = gate * HDIM + h0 + warp_w * 4 + jj;
        float v = (k < HDIM) ? U[(size_t)k * G4 + col]
                             : W[(size_t)(k - HDIM) * G4 + col];
        zh[nl * ZSTR + k] = __float2half(v);
    }
    // per-thread bias: all 4 gates of hid H
    const int H  = h0 + warp * 4 + (lane & 3);
    const float bI = bias[H];
    const float bF = bias[HDIM + H];
    const float bG = bias[2 * HDIM + H];
    const float bO = bias[3 * HDIM + H];

    if (tid == 0) {
        if (gc == 0) g_step[grp][0] = 0;   // replay-safe reset
        mbar_init(mbar, THREADS);
    }
    __syncthreads();

    // hoist ALL B fragments into registers (loop-invariant across 1024 steps)
    const int brow = warp * 16 + ((lane & 7) | ((lane >> 1) & 8));
    const uint32_t bHiA = smb + OFF_Z + ((brow * ZSTR + (lane & 8)) << 1);
    unsigned bfr[NCH][4];
    #pragma unroll
    for (int kc = 0; kc < NCH; kc++)
        ldsm4(bfr[kc], bHiA + kc * 32);

    if (tid == 0) bar_all(NGRP * NCTA);
    __syncthreads();

    const int r = lane >> 2;
    // store address: lane_t = (r<<2)|((warp&1)<<1)|((lane&3)>>1), j_t pair adjacent
    const uint32_t stOff = (((r << 2) | ((warp & 1) << 1) | ((lane & 3) >> 1)) << 4)
                           + ((warp >> 1) << 3);
    float c0 = 0.f, c1 = 0.f;

    for (int s = 0; s < SEQ; s++) {
        // 4 accumulator chains: [t][even/odd]; t0 = gates i,f ; t1 = gates g,o
        float accA[2][4], accB[2][4];
        accA[0][0] = bI; accA[0][1] = bF; accA[0][2] = bI; accA[0][3] = bF;
        accA[1][0] = bG; accA[1][1] = bO; accA[1][2] = bG; accA[1][3] = bO;
        #pragma unroll
        for (int t = 0; t < 2; t++) {
            accB[t][0] = 0.f; accB[t][1] = 0.f;
            accB[t][2] = 0.f; accB[t][3] = 0.f;
        }

        // x fragment loads (issued before the poll; latency hidden)
        uint32_t xv[NCH_X][4];
        {
            const uint4* xb = (const uint4*)(g_xfrag +
                (((size_t)grp * SEQ + s) * NCH_X) * 128 + lane * 4);
            #pragma unroll
            for (int kx = 0; kx < NCH_X; kx++) {
                uint4 t4 = __ldg(xb + kx * 32);
                xv[kx][0] = t4.x; xv[kx][1] = t4.y; xv[kx][2] = t4.z; xv[kx][3] = t4.w;
            }
        }

        const uint32_t aStg = smb + ((s & 1) ? OFF_A1 : OFF_A0) + lane * 16;

        if (s > 0) {
            poll_cnt(grp, 128 * s);
            const char* hsrc = (const char*)g_hfrag +
                ((size_t)((s & 1) * NGRP + grp) * NCTA) * 512 + lane * 16;
            #pragma unroll
            for (int i = 0; i < 8; i++) {
                int kc = warp * 8 + i;
                cpasync16(aStg + kc * 512, hsrc + kc * 512);
            }
            cp_mbar_arrive(mbar);
        }

        // x-part GEMM (regs only; overlaps cp.async flight)
        #pragma unroll
        for (int kx = 0; kx < NCH_X; kx++) {
            float* d0 = (kx & 1) ? accB[0] : accA[0];
            float* d1 = (kx & 1) ? accB[1] : accA[1];
            mma_f16(d0, xv[kx], bfr[NCH_H + kx]);
            mma_f16(d1, xv[kx], bfr[NCH_H + kx] + 2);
        }

        // h-part GEMM (after mbarrier parity wait; no syncthreads)
        if (s > 0) {
            mbar_wait(mbar, (s - 1) & 1);
            #pragma unroll
            for (int kc = 0; kc < NCH_H; kc++) {
                unsigned av[4];
                lds128(av, aStg + kc * 512);
                float* d0 = (kc & 1) ? accB[0] : accA[0];
                float* d1 = (kc & 1) ? accB[1] : accA[1];
                mma_f16(d0, av, bfr[kc]);
                mma_f16(d1, av, bfr[kc] + 2);
            }
        }

        // register epilogue: gate-complete, NO gate-exchange shfls
        char* hdst = (char*)g_hfrag +
            ((size_t)(((s + 1) & 1) * NGRP + grp) * NCTA + gc) * 512;
        // row r
        float gi0 = accA[0][0] + accB[0][0], gf0 = accA[0][1] + accB[0][1];
        float gg0 = accA[1][0] + accB[1][0], go0 = accA[1][1] + accB[1][1];
        // row r+8
        float gi1 = accA[0][2] + accB[0][2], gf1 = accA[0][3] + accB[0][3];
        float gg1 = accA[1][2] + accB[1][2], go1 = accA[1][3] + accB[1][3];

        c0 = fsig_f(gf0) * c0 + fsig_f(gi0) * ftanh_f(gg0);
        float h0v = fsig_f(go0) * ftanh_f(c0);
        c1 = fsig_f(gf1) * c1 + fsig_f(gi1) * ftanh_f(gg1);
        float h1v = fsig_f(go1) * ftanh_f(c1);

        unsigned hb0 = (unsigned)__half_as_ushort(__float2half(h0v));
        unsigned hb1 = (unsigned)__half_as_ushort(__float2half(h1v));
        unsigned pb0 = __shfl_xor_sync(0xffffffffu, hb0, 1);
        unsigned pb1 = __shfl_xor_sync(0xffffffffu, hb1, 1);
        if ((lane & 1) == 0) {
            uint2 w2;
            w2.x = hb0 | (pb0 << 16);    // j_t even : row r word
            w2.y = hb1 | (pb1 << 16);    // j_t odd  : row r+8 word
            *(uint2*)(hdst + stOff) = w2;
        }
        if (s == SEQ - 1) {
            g_hfin[b0 + r][H]     = h0v;
            g_hfin[b0 + r + 8][H] = h1v;
        }
        if (lane == 0) release_inc(grp);
    }

    // FC head: one CTA per group, exact fp32 h
    if (gc == 0) {
        poll_cnt(grp, 128 * SEQ);
        int b = tid >> 3, l8 = tid & 7;
        float a7[7] = {0.f, 0.f, 0.f, 0.f, 0.f, 0.f, 0.f};
        for (int it = 0; it < HDIM / 8; it++) {
            int k = l8 + it * 8;
            float hv;
            asm volatile("ld.relaxed.gpu.global.f32 %0, [%1];"
                         : "=f"(hv) : "l"(&g_hfin[b0 + b][k]));
            #pragma unroll
            for (int o = 0; o < 7; o++) a7[o] += hv * fc_w[k * 7 + o];
        }
        #pragma unroll
        for (int o = 0; o < 7; o++) {
            a7[o] += __shfl_xor_sync(0xffffffffu, a7[o], 4);
            a7[o] += __shfl_xor_sync(0xffffffffu, a7[o], 2);
            a7[o] += __shfl_xor_sync(0xffffffffu, a7[o], 1);
        }
        if (l8 == 0)
            #pragma unroll
            for (int o = 0; o < 7; o++) out[(b0 + b) * 7 + o] = a7[o] + fc_b[o];
    }
}

extern "C" void kernel_launch(void* const* d_in, const int* in_sizes, int n_in,
                              void* d_out, int out_size)
{
    (void)in_sizes; (void)n_in; (void)out_size;
    const float* x    = (const float*)d_in[0];
    const float* W    = (const float*)d_in[1];
    const float* U    = (const float*)d_in[2];
    const float* bias = (const float*)d_in[3];
    const float* fc_w = (const float*)d_in[4];
    const float* fc_b = (const float*)d_in[5];

    cudaFuncSetAttribute(lstm_kernel,
                         cudaFuncAttributeMaxDynamicSharedMemorySize, SMEM_SZ);
    xsplit_kernel<<<BATCH * SEQ * IDIM / 1024, 256>>>(x);
    lstm_kernel<<<NGRP * NCTA, THREADS, SMEM_SZ>>>(W, U, bias, fc_w, fc_b, (float*)d_out);
}

// round 16
// speedup vs baseline: 1.0027x; 1.0027x over previous
#include <cuda_runtime.h>
#include <cuda_fp16.h>
#include <cstdint>

#define BATCH   64
#define SEQ     1024
#define IDIM    128
#define HDIM    512
#define G4      2048
#define KTOT    640
#define NGRP    4
#define GB      16
#define NCTA    32
#define HC      16
#define NL      64
#define THREADS 128
#define NCH_H   32
#define NCH_X   8
#define NCH     40

#define ZSTR     648
#define OFF_Z    0
#define OFF_A0   (NL * ZSTR * 2)            // 82944 : staging buf 0 (16KB)
#define OFF_A1   (OFF_A0 + NCH_H * 512)     // 99328 : staging buf 1 (16KB)
#define OFF_MBAR (OFF_A1 + NCH_H * 512)     // 115712
#define SMEM_SZ  (OFF_MBAR + 16)            // 115728 B

// ---- global scratch (static) -------------------------------------------------
__device__ uint32_t g_xfrag[(size_t)NGRP * SEQ * NCH_X * 128];  // x in frag layout
__device__ uint32_t g_hfrag[2 * NGRP * NCTA * 128];             // ping-pong h chunks
__device__ float    g_hfin[BATCH][HDIM];                        // exact final h
__device__ int      g_step[NGRP][4][32];    // 4 striped 128B-padded counters/group
__device__ int      g_cnt, g_gen;

// ---- prologue-only global barrier (replay-safe) ------------------------------
__device__ __forceinline__ void bar_all(int n)
{
    int my;
    asm volatile("ld.acquire.gpu.global.b32 %0, [%1];" : "=r"(my) : "l"(&g_gen));
    __threadfence();
    if (atomicAdd(&g_cnt, 1) == n - 1) {
        atomicExch(&g_cnt, 0);
        __threadfence();
        atomicAdd(&g_gen, 1);
    } else {
        int v;
        do { asm volatile("ld.acquire.gpu.global.b32 %0, [%1];" : "=r"(v) : "l"(&g_gen)); }
        while (v == my);
    }
}

// 4-line striped poll: lane reads line (lane&3); exit when ALL lines >= need
__device__ __forceinline__ void poll4(int g, int lane, int need)
{
    const int* p = &g_step[g][lane & 3][0];
    int v;
    do { asm volatile("ld.acquire.gpu.global.b32 %0, [%1];" : "=r"(v) : "l"(p)); }
    while (__any_sync(0xffffffffu, v < need));
}
// warp w releases to its own stripe -> 4x less same-address RED serialization
__device__ __forceinline__ void release_inc4(int g, int w)
{
    asm volatile("red.add.release.gpu.global.s32 [%0], 1;"
                 :: "l"(&g_step[g][w][0]) : "memory");
}

__device__ __forceinline__ void cpasync16(uint32_t dst, const void* src)
{
    asm volatile("cp.async.cg.shared.global [%0], [%1], 16;" :: "r"(dst), "l"(src));
}
// .noinc is load-bearing (R8 deadlock without it)
__device__ __forceinline__ void cp_mbar_arrive(uint32_t mbar)
{
    asm volatile("cp.async.mbarrier.arrive.noinc.shared::cta.b64 [%0];"
                 :: "r"(mbar) : "memory");
}
__device__ __forceinline__ void mbar_init(uint32_t mbar, int cnt)
{
    asm volatile("mbarrier.init.shared.b64 [%0], %1;" :: "r"(mbar), "r"(cnt) : "memory");
}
__device__ __forceinline__ void mbar_wait(uint32_t mbar, uint32_t parity)
{
    asm volatile(
        "{\n\t"
        ".reg .pred P;\n\t"
        "WAIT_%=:\n\t"
        "mbarrier.try_wait.parity.acquire.cta.shared::cta.b64 P, [%0], %1, 0x989680;\n\t"
        "@P bra.uni DONE_%=;\n\t"
        "bra.uni WAIT_%=;\n\t"
        "DONE_%=:\n\t"
        "}"
        :: "r"(mbar), "r"(parity) : "memory");
}

__device__ __forceinline__ void lds128(unsigned r[4], uint32_t a)
{
    asm volatile("ld.shared.v4.b32 {%0,%1,%2,%3}, [%4];"
                 : "=r"(r[0]), "=r"(r[1]), "=r"(r[2]), "=r"(r[3]) : "r"(a));
}
__device__ __forceinline__ void ldsm4(unsigned r[4], uint32_t a)
{
    asm volatile("ldmatrix.sync.aligned.m8n8.x4.shared.b16 {%0,%1,%2,%3}, [%4];"
                 : "=r"(r[0]), "=r"(r[1]), "=r"(r[2]), "=r"(r[3]) : "r"(a));
}
__device__ __forceinline__ void mma_f16(float* d, const unsigned* a, const unsigned* b)
{
    asm volatile(
        "mma.sync.aligned.m16n8k16.row.col.f32.f16.f16.f32 "
        "{%0,%1,%2,%3}, {%4,%5,%6,%7}, {%8,%9}, {%0,%1,%2,%3};\n"
        : "+f"(d[0]), "+f"(d[1]), "+f"(d[2]), "+f"(d[3])
        : "r"(a[0]), "r"(a[1]), "r"(a[2]), "r"(a[3]), "r"(b[0]), "r"(b[1]));
}

// fast activations (validated R14): single tanh.approx MUFU each
__device__ __forceinline__ float ftanh_f(float x)
{
    float y;
    asm("tanh.approx.f32 %0, %1;" : "=f"(y) : "f"(x));
    return y;
}
__device__ __forceinline__ float fsig_f(float x)
{
    return fmaf(0.5f, ftanh_f(0.5f * x), 0.5f);
}

// ---- x -> fp16 fragment-ready layout (validated) -----------------------------
extern "C" __global__ void xsplit_kernel(const float* __restrict__ x)
{
    int gid = blockIdx.x * 256 + threadIdx.x;
    int i0 = (gid & 31) * 4;
    int s  = (gid >> 5) & (SEQ - 1);
    int b  = gid >> 15;
    float4 v = *(const float4*)(x + ((size_t)b * SEQ + s) * IDIM + i0);
    int bl = b & 15, grp = b >> 4;
    int kx = i0 >> 4, kl = i0 & 15;
    int lane = ((bl & 7) << 2) | ((kl & 7) >> 1);
    int j    = ((kl >> 3) << 1) | (bl >> 3);
    uint32_t u0 = (uint32_t)__half_as_ushort(__float2half(v.x)) |
                  ((uint32_t)__half_as_ushort(__float2half(v.y)) << 16);
    uint32_t u1 = (uint32_t)__half_as_ushort(__float2half(v.z)) |
                  ((uint32_t)__half_as_ushort(__float2half(v.w)) << 16);
    size_t base = (((size_t)grp * SEQ + s) * NCH_X + kx) * 128;
    g_xfrag[base + lane * 4 + j]       = u0;
    g_xfrag[base + (lane + 1) * 4 + j] = u1;
}

// ---- persistent LSTM: R14 structure exactly, striped release counters --------
extern "C" __global__ void __launch_bounds__(THREADS, 1)
lstm_kernel(const float* __restrict__ W, const float* __restrict__ U,
            const float* __restrict__ bias,
            const float* __restrict__ fc_w, const float* __restrict__ fc_b,
            float* __restrict__ out)
{
    extern __shared__ char smem[];
    __half* zh = (__half*)(smem + OFF_Z);

    const int tid  = threadIdx.x;
    const int lane = tid & 31;
    const int warp = tid >> 5;
    const int grp  = blockIdx.x >> 5;
    const int gc   = blockIdx.x & 31;
    const int b0   = grp * GB;
    const int h0   = gc * HC;
    const uint32_t smb  = (uint32_t)__cvta_generic_to_shared(smem);
    const uint32_t mbar = smb + OFF_MBAR;

    // weights into smem, gate-interleaved local cols: nl -> hid=nl>>2, gate=nl&3
    for (int idx = tid; idx < KTOT * NL; idx += THREADS) {
        int k = idx >> 6, nl = idx & 63;
        int col = (nl & 3) * HDIM + h0 + (nl >> 2);
        float v = (k < HDIM) ? U[(size_t)k * G4 + col]
                             : W[(size_t)(k - HDIM) * G4 + col];
        zh[nl * ZSTR + k] = __float2half(v);
    }
    const int q = (lane >> 1) & 1;
    float bv[2][2];
    #pragma unroll
    for (int t = 0; t < 2; t++) {
        int hid = h0 + warp * 4 + t * 2 + q;
        #pragma unroll
        for (int j = 0; j < 2; j++)
            bv[t][j] = bias[(2 * (lane & 1) + j) * HDIM + hid];
    }
    if (tid == 0) {
        if (gc == 0)
            for (int w = 0; w < 4; w++) g_step[grp][w][0] = 0;  // replay-safe reset
        mbar_init(mbar, THREADS);
    }
    __syncthreads();

    // hoist ALL B fragments into registers (loop-invariant across 1024 steps)
    const int brow = warp * 16 + ((lane & 7) | ((lane >> 1) & 8));
    const uint32_t bHiA = smb + OFF_Z + ((brow * ZSTR + (lane & 8)) << 1);
    unsigned bfr[NCH][4];
    #pragma unroll
    for (int kc = 0; kc < NCH; kc++)
        ldsm4(bfr[kc], bHiA + kc * 32);

    if (tid == 0) bar_all(NGRP * NCTA);
    __syncthreads();

    const int r = lane >> 2;
    const int jt_c = (warp >> 1) << 1;
    const int lt_c = (warp & 1) << 1;
    float c0 = 0.f, c1 = 0.f;

    for (int s = 0; s < SEQ; s++) {
        // 4 accumulator chains: [t][even/odd]
        float accA[2][4], accB[2][4];
        #pragma unroll
        for (int t = 0; t < 2; t++) {
            accA[t][0] = bv[t][0]; accA[t][1] = bv[t][1];
            accA[t][2] = bv[t][0]; accA[t][3] = bv[t][1];
            accB[t][0] = 0.f; accB[t][1] = 0.f;
            accB[t][2] = 0.f; accB[t][3] = 0.f;
        }

        // x fragment loads (issued before the poll; latency hidden)
        uint32_t xv[NCH_X][4];
        {
            const uint4* xb = (const uint4*)(g_xfrag +
                (((size_t)grp * SEQ + s) * NCH_X) * 128 + lane * 4);
            #pragma unroll
            for (int kx = 0; kx < NCH_X; kx++) {
                uint4 t4 = __ldg(xb + kx * 32);
                xv[kx][0] = t4.x; xv[kx][1] = t4.y; xv[kx][2] = t4.z; xv[kx][3] = t4.w;
            }
        }

        const uint32_t aStg = smb + ((s & 1) ? OFF_A1 : OFF_A0) + lane * 16;

        if (s > 0) {
            poll4(grp, lane, 32 * s);
            const char* hsrc = (const char*)g_hfrag +
                ((size_t)((s & 1) * NGRP + grp) * NCTA) * 512 + lane * 16;
            #pragma unroll
            for (int i = 0; i < 8; i++) {
                int kc = warp * 8 + i;
                cpasync16(aStg + kc * 512, hsrc + kc * 512);
            }
            cp_mbar_arrive(mbar);
        }

        // x-part GEMM (regs only; overlaps cp.async flight)
        #pragma unroll
        for (int kx = 0; kx < NCH_X; kx++) {
            float* d0 = (kx & 1) ? accB[0] : accA[0];
            float* d1 = (kx & 1) ? accB[1] : accA[1];
            mma_f16(d0, xv[kx], bfr[NCH_H + kx]);
            mma_f16(d1, xv[kx], bfr[NCH_H + kx] + 2);
        }

        // h-part GEMM (after mbarrier parity wait; no syncthreads)
        if (s > 0) {
            mbar_wait(mbar, (s - 1) & 1);
            #pragma unroll
            for (int kc = 0; kc < NCH_H; kc++) {
                unsigned av[4];
                lds128(av, aStg + kc * 512);
                float* d0 = (kc & 1) ? accB[0] : accA[0];
                float* d1 = (kc & 1) ? accB[1] : accA[1];
                mma_f16(d0, av, bfr[kc]);
                mma_f16(d1, av, bfr[kc] + 2);
            }
        }

        // register epilogue: combine chains, gate exchange, packed h store
        char* hdst = (char*)g_hfrag +
            ((size_t)(((s + 1) & 1) * NGRP + grp) * NCTA + gc) * 512;
        #pragma unroll
        for (int t = 0; t < 2; t++) {
            float a0 = accA[t][0] + accB[t][0];
            float a1 = accA[t][1] + accB[t][1];
            float a2 = accA[t][2] + accB[t][2];
            float a3 = accA[t][3] + accB[t][3];
            float e0 = __shfl_xor_sync(0xffffffffu, a0, 1);
            float e1 = __shfl_xor_sync(0xffffffffu, a1, 1);
            float e2 = __shfl_xor_sync(0xffffffffu, a2, 1);
            float e3 = __shfl_xor_sync(0xffffffffu, a3, 1);
            float gi, gf, gg, go;
            int bidx;
            if ((lane & 1) == 0) {
                gi = a0; gf = a1; gg = e0; go = e1; bidx = r;
            } else {
                gi = e2; gf = e3; gg = a2; go = a3; bidx = r + 8;
            }
            float i_ = fsig_f(gi), f_ = fsig_f(gf), g_ = ftanh_f(gg), o_ = fsig_f(go);
            float& cc = t ? c1 : c0;
            cc = f_ * cc + i_ * g_;
            float h = o_ * ftanh_f(cc);
            unsigned hb = (unsigned)__half_as_ushort(__float2half(h));
            unsigned ob = __shfl_xor_sync(0xffffffffu, hb, 2);
            if (q == 0) {
                unsigned word = hb | (ob << 16);
                int lt = ((bidx & 7) << 2) | lt_c | t;
                int jt = jt_c | (bidx >> 3);
                *(unsigned*)(hdst + lt * 16 + jt * 4) = word;
            }
            if (s == SEQ - 1) g_hfin[b0 + bidx][h0 + warp * 4 + t * 2 + q] = h;
        }
        if (lane == 0) release_inc4(grp, warp);
    }

    // FC head: one CTA per group, exact fp32 h
    if (gc == 0) {
        poll4(grp, lane, 32 * SEQ);
        int b = tid >> 3, l8 = tid & 7;
        float a7[7] = {0.f, 0.f, 0.f, 0.f, 0.f, 0.f, 0.f};
        for (int it = 0; it < HDIM / 8; it++) {
            int k = l8 + it * 8;
            float hv;
            asm volatile("ld.relaxed.gpu.global.f32 %0, [%1];"
                         : "=f"(hv) : "l"(&g_hfin[b0 + b][k]));
            #pragma unroll
            for (int o = 0; o < 7; o++) a7[o] += hv * fc_w[k * 7 + o];
        }
        #pragma unroll
        for (int o = 0; o < 7; o++) {
            a7[o] += __shfl_xor_sync(0xffffffffu, a7[o], 4);
            a7[o] += __shfl_xor_sync(0xffffffffu, a7[o], 2);
            a7[o] += __shfl_xor_sync(0xffffffffu, a7[o], 1);
        }
        if (l8 == 0)
            #pragma unroll
            for (int o = 0; o < 7; o++) out[(b0 + b) * 7 + o] = a7[o] + fc_b[o];
    }
}

extern "C" void kernel_launch(void* const* d_in, const int* in_sizes, int n_in,
                              void* d_out, int out_size)
{
    (void)in_sizes; (void)n_in; (void)out_size;
    const float* x    = (const float*)d_in[0];
    const float* W    = (const float*)d_in[1];
    const float* U    = (const float*)d_in[2];
    const float* bias = (const float*)d_in[3];
    const float* fc_w = (const float*)d_in[4];
    const float* fc_b = (const float*)d_in[5];

    cudaFuncSetAttribute(lstm_kernel,
                         cudaFuncAttributeMaxDynamicSharedMemorySize, SMEM_SZ);
    xsplit_kernel<<<BATCH * SEQ * IDIM / 1024, 256>>>(x);
    lstm_kernel<<<NGRP * NCTA, THREADS, SMEM_SZ>>>(W, U, bias, fc_w, fc_b, (float*)d_out);
}